// round 8
// baseline (speedup 1.0000x reference)
#include <cuda_runtime.h>

// Fixed problem shape
#define BB 4
#define CC 19
#define HH 256
#define WW 256
#define HW (HH * WW)
#define CHW (CC * HW)
#define RAD 10
#define TS 32
#define EW (TS + 2 * RAD)   // 52 halo rows
#define NBLK 256            // total blocks; must be <= 2*148 for co-residency

// Scratch (device globals; self-resetting each replay)
__device__ float g_ent[BB * HW];
__device__ float g_kl[BB * HW];
__device__ unsigned char g_fg[BB * HW];
__device__ int g_entmax[BB];        // entropy > 0 -> int atomicMax is order-preserving
__device__ double g_sum_wkl;
__device__ double g_sum_w;
__device__ unsigned int g_arr;      // barrier arrive
__device__ unsigned int g_dep;      // barrier depart
__device__ unsigned int g_done;     // finalize election

// ---------------------------------------------------------------------------
// Single fused kernel: phase A (channel math, 1 px/thread, 64 warps/SM) ->
// software grid barrier (2 CTAs/SM guaranteed by __launch_bounds__(1024,2)) ->
// phase B (bounded EDT + weights + reduction + fused finalize).
// ---------------------------------------------------------------------------
__global__ void __launch_bounds__(1024, 2) ofkd_fused(
    const float* __restrict__ student, const float* __restrict__ teacher,
    float* __restrict__ out)
{
    const int b   = blockIdx.y;
    const int tid = threadIdx.x;

    // ================= Phase A: channel-wise math, 1 pixel/thread ==========
    // Z = sum e^t, S = sum t e^t, T = sum s e^t, Zs = sum e^s   (t,s = logit/4)
    // ent = logZ - S/Z ;  kl = (S-T)/Z - logZ + logZs
    {
        const int p = blockIdx.x * 1024 + tid;
        const size_t base = (size_t)b * CHW + p;

        float Z = 0.f, S = 0.f, Tt = 0.f, Zs = 0.f;
        float t0, mx = -1e30f;
#pragma unroll
        for (int c = 0; c < CC; c++) {
            float tv = __ldg(teacher + base + (size_t)c * HW) * 0.25f;
            float sv = __ldg(student + base + (size_t)c * HW) * 0.25f;
            float e = __expf(tv);
            Z += e;
            S = fmaf(e, tv, S);
            Tt = fmaf(e, sv, Tt);
            Zs += __expf(sv);
            if (c == 0) t0 = tv;
            else        mx = fmaxf(mx, tv);
        }
        const float lZ = __logf(Z);
        const float ent = lZ - S / Z;
        const float kl = (S - Tt) / Z - lZ + __logf(Zs);

        const int idx = b * HW + p;
        g_ent[idx] = ent;
        g_kl[idx] = kl;
        g_fg[idx] = (mx > t0) ? 1 : 0;   // argmax != 0 (ties -> class 0)

        float entm = ent;
#pragma unroll
        for (int o = 16; o > 0; o >>= 1)
            entm = fmaxf(entm, __shfl_xor_sync(0xFFFFFFFF, entm, o));
        __shared__ float smax[32];
        if ((tid & 31) == 0) smax[tid >> 5] = entm;
        __syncthreads();
        if (tid < 32) {
            float m = smax[tid];
#pragma unroll
            for (int o = 16; o > 0; o >>= 1)
                m = fmaxf(m, __shfl_xor_sync(0xFFFFFFFF, m, o));
            if (tid == 0) atomicMax(&g_entmax[b], __float_as_int(m));
        }
    }

    // ================= Grid barrier (self-resetting) ========================
    __threadfence();          // each thread releases its own global writes
    __syncthreads();
    if (tid == 0) {
        atomicAdd(&g_arr, 1u);
        while (atomicAdd(&g_arr, 0u) < NBLK) { }
        unsigned int t = atomicAdd(&g_dep, 1u);
        if (t == NBLK - 1) {  // all blocks past the spin: reset for next replay
            atomicExch(&g_arr, 0u);
            atomicExch(&g_dep, 0u);
        }
    }
    __syncthreads();

    // ================= Phase B: bounded EDT + weights =======================
    const int i0 = (blockIdx.x >> 3) * TS;
    const int j0 = (blockIdx.x & 7) * TS;
    const int ty = tid >> 5;           // tile row 0..31
    const int tx = tid & 31;           // tile col 0..31

    // prefetch ent/kl for this pixel (coalesced; L2-resident)
    const int pidx = b * HW + (i0 + ty) * WW + j0 + tx;
    const float entv = g_ent[pidx];
    const float klv  = g_kl[pidx];
    const float Hm = __int_as_float(g_entmax[b]);

    __shared__ unsigned char sfg[EW][56];   // fg halo: col cc = global j0-12+cc
    __shared__ unsigned char svv[TS][56];   // vertical min-d^2

    // fg halo: 52 rows x 14 aligned u32 words (single step, tid < 728)
    if (tid < EW * 14) {
        int r = tid / 14, k = tid - r * 14;
        int gi = i0 - RAD + r;
        int g0 = j0 - 12 + 4 * k;           // j0 % 32 == 0 -> g0 % 4 == 0
        unsigned int word = 0;
        if (gi >= 0 && gi < HH) {
            const unsigned char* rowp = g_fg + b * HW + gi * WW;
            if (g0 >= 0 && g0 + 3 < WW) {
                word = *(const unsigned int*)(rowp + g0);
            } else {
#pragma unroll
                for (int bb = 0; bb < 4; bb++) {
                    int gj = g0 + bb;
                    if (gj >= 0 && gj < WW)
                        word |= (unsigned int)rowp[gj] << (8 * bb);
                }
            }
        }
        *(unsigned int*)&sfg[r][4 * k] = word;
    }
    __syncthreads();

    // vertical 21-tap min, byte SIMD (term = 200 - fg*(200-d^2)), 2 chains
    if (tid < TS * 14) {
        int r = tid / 14, wc = (tid - r * 14) * 4;
        unsigned int va = 0xC8C8C8C8u, vb = 0xC8C8C8C8u;
#pragma unroll
        for (int dr = 0; dr < 21; dr += 2) {
            unsigned int f4 = *(const unsigned int*)&sfg[r + dr][wc];
            int d = dr - RAD;
            va = __vminu4(va, 0xC8C8C8C8u - f4 * (unsigned int)(200 - d * d));
        }
#pragma unroll
        for (int dr = 1; dr < 21; dr += 2) {
            unsigned int f4 = *(const unsigned int*)&sfg[r + dr][wc];
            int d = dr - RAD;
            vb = __vminu4(vb, 0xC8C8C8C8u - f4 * (unsigned int)(200 - d * d));
        }
        *(unsigned int*)&svv[r][wc] = __vminu4(va, vb);
    }
    __syncthreads();

    // horizontal 21-tap min: independent byte-LDS, 3 split chains
    int m0 = 300, m1 = 300, m2 = 300;
#pragma unroll
    for (int s = 0; s < 7; s++) {
        int dd = s - RAD;
        m0 = min(m0, dd * dd + (int)svv[ty][tx + 2 + s]);
    }
#pragma unroll
    for (int s = 7; s < 14; s++) {
        int dd = s - RAD;
        m1 = min(m1, dd * dd + (int)svv[ty][tx + 2 + s]);
    }
#pragma unroll
    for (int s = 14; s < 21; s++) {
        int dd = s - RAD;
        m2 = min(m2, dd * dd + (int)svv[ty][tx + 2 + s]);
    }
    const int d2 = min(m0, min(m1, m2));

    // weight for this pixel
    float a_wkl = 0.f, a_w = 0.f;
    if (d2 <= RAD * RAD) {
        float wd = __expf((float)d2 * (-1.0f / 50.0f));  // 2*sigma^2 = 50
        float bnd = 0.f;
        if (sfg[ty + RAD][tx + 12]) {
            bool er = sfg[ty + RAD - 1][tx + 12] && sfg[ty + RAD + 1][tx + 12]
                   && sfg[ty + RAD][tx + 11] && sfg[ty + RAD][tx + 13];
            if (!er) bnd = 1.f;
        }
        float conf = 0.1f + 0.9f * (1.f - entv / (Hm + 1e-8f));
        float wgt = wd * (1.f + bnd) * conf;
        a_wkl = wgt * klv;
        a_w   = wgt;
    }

    // reduce (32 warps) + fused finalize
#pragma unroll
    for (int o = 16; o > 0; o >>= 1) {
        a_wkl += __shfl_xor_sync(0xFFFFFFFF, a_wkl, o);
        a_w   += __shfl_xor_sync(0xFFFFFFFF, a_w, o);
    }
    __shared__ float r1[32], r2[32];
    if ((tid & 31) == 0) { r1[tid >> 5] = a_wkl; r2[tid >> 5] = a_w; }
    __syncthreads();

    if (tid < 32) {
        float s1 = r1[tid], s2 = r2[tid];
#pragma unroll
        for (int o = 16; o > 0; o >>= 1) {
            s1 += __shfl_xor_sync(0xFFFFFFFF, s1, o);
            s2 += __shfl_xor_sync(0xFFFFFFFF, s2, o);
        }
        if (tid == 0) {
            atomicAdd(&g_sum_wkl, (double)s1);
            atomicAdd(&g_sum_w, (double)s2);
            __threadfence();
            unsigned int t = atomicAdd(&g_done, 1u);
            if (t == NBLK - 1) {  // last block: finalize + reset for next replay
                double swkl = atomicAdd(&g_sum_wkl, 0.0);
                double sw   = atomicAdd(&g_sum_w, 0.0);
                out[0] = (float)(16.0 * swkl / (sw + 1e-8));
                g_sum_wkl = 0.0;
                g_sum_w = 0.0;
#pragma unroll
                for (int bb = 0; bb < BB; bb++) g_entmax[bb] = 0;
                atomicExch(&g_done, 0u);
            }
        }
    }
}

extern "C" void kernel_launch(void* const* d_in, const int* in_sizes, int n_in,
                              void* d_out, int out_size)
{
    const float* student = (const float*)d_in[0];
    const float* teacher = (const float*)d_in[1];
    float* out = (float*)d_out;

    ofkd_fused<<<dim3(64, BB), 1024>>>(student, teacher, out);
}